// round 15
// baseline (speedup 1.0000x reference)
#include <cuda_runtime.h>
#include <cuda_bf16.h>
#include <math.h>
#include <stdint.h>

#define N_SMP 32
#define CH    128
#define HWPX  4096
#define KTOT  1152
#define KC    64
#define NCHUNK 18
#define WFRAG_PER_N 73728   // u32 per sample: 18 chunk * 4 kstep * 8 m16 * 32 lane * 4 reg

// ---------------- device scratch ----------------
__device__ uint32_t g_wfh[2][N_SMP * WFRAG_PER_N];
__device__ uint32_t g_wfl[2][N_SMP * WFRAG_PER_N];
__device__ float    g_gam[2][N_SMP * CH * CH];
__device__ float    g_bet[2][N_SMP * CH * CH];
__device__ float    g_y[2][N_SMP * CH * HWPX];   // per-layer conv outputs
__device__ float    g_stats[2][N_SMP * CH * 2];
__device__ float    g_affp[N_SMP * CH * 2];      // fused adain-1 affine (g,b)
__device__ float    g_bias[2][N_SMP * CH];
__device__ float    g_adg[2][N_SMP * CH];
__device__ float    g_adb[2][N_SMP * CH];

// ---------------- small per-sample vectors ----------------
__global__ void modvec_kernel(const float* __restrict__ task, const float* __restrict__ style,
    const float* __restrict__ b1, const float* __restrict__ tb1w, const float* __restrict__ tb1b,
    const float* __restrict__ ad1w, const float* __restrict__ ad1b,
    const float* __restrict__ b2, const float* __restrict__ tb2w, const float* __restrict__ tb2b,
    const float* __restrict__ ad2w, const float* __restrict__ ad2b)
{
    __shared__ float ts[512], ss[512];
    const int n = blockIdx.x;
    const int co = threadIdx.x;
    for (int k = co; k < 512; k += 128) { ts[k] = task[n*512+k]; ss[k] = style[n*512+k]; }
    __syncthreads();
    float a0=0.f,a1=0.f,a2=0.f,a3=0.f,a4=0.f,a5=0.f;
    for (int k = 0; k < 512; k++) {
        float t = ts[k], s = ss[k];
        a0 = fmaf(tb1w[co*512+k],       t, a0);
        a1 = fmaf(ad1w[co*512+k],       s, a1);
        a2 = fmaf(ad1w[(co+128)*512+k], s, a2);
        a3 = fmaf(tb2w[co*512+k],       t, a3);
        a4 = fmaf(ad2w[co*512+k],       s, a4);
        a5 = fmaf(ad2w[(co+128)*512+k], s, a5);
    }
    const float se = 0.0625f;
    g_bias[0][n*128+co] = b1[co] + a0*se + tb1b[co];
    g_adg [0][n*128+co] = a1*se + ad1b[co];
    g_adb [0][n*128+co] = a2*se + ad1b[co+128];
    g_bias[1][n*128+co] = b2[co] + a3*se + tb2b[co];
    g_adg [1][n*128+co] = a4*se + ad2b[co];
    g_adb [1][n*128+co] = a5*se + ad2b[co+128];
}

// ---------------- gamma/beta GEMM -> coalesced gamma/beta stores ---------
#define GB_JT 64
#define GB_KC 16
__global__ __launch_bounds__(128)
void gemm_wmod_kernel(const float* __restrict__ task, const float* __restrict__ tw,
                      const float* __restrict__ tb, int layer)
{
    __shared__ float As[GB_KC][GB_JT];
    __shared__ float Bs[GB_KC][32];
    const int tid = threadIdx.x;
    const int jb  = blockIdx.x * GB_JT;
    const int jg  = tid & 15;
    const int ng  = tid >> 4;

    if (blockIdx.x < 64) g_stats[layer][blockIdx.x * 128 + tid] = 0.f;

    float acc[4][4] = {};

    for (int k0 = 0; k0 < 512; k0 += GB_KC) {
        #pragma unroll
        for (int t = 0; t < 2; t++) {
            int li  = tid*2 + t;
            int row = li >> 2;
            int kq  = (li & 3) * 4;
            float4 v = *(const float4*)(tw + (size_t)(jb + row)*512 + k0 + kq);
            As[kq+0][row] = v.x; As[kq+1][row] = v.y; As[kq+2][row] = v.z; As[kq+3][row] = v.w;
        }
        {
            int nn = tid >> 2;
            int kq = (tid & 3) * 4;
            float4 v = *(const float4*)(task + (size_t)nn*512 + k0 + kq);
            Bs[kq+0][nn] = v.x; Bs[kq+1][nn] = v.y; Bs[kq+2][nn] = v.z; Bs[kq+3][nn] = v.w;
        }
        __syncthreads();
        #pragma unroll
        for (int k = 0; k < GB_KC; k++) {
            float4 a = *(const float4*)&As[k][jg*4];
            float4 b = *(const float4*)&Bs[k][ng*4];
            float av[4] = {a.x,a.y,a.z,a.w};
            float bv[4] = {b.x,b.y,b.z,b.w};
            #pragma unroll
            for (int i = 0; i < 4; i++)
                #pragma unroll
                for (int j = 0; j < 4; j++)
                    acc[i][j] = fmaf(av[i], bv[j], acc[i][j]);
        }
        __syncthreads();
    }

    const float se = 0.0625f;
    const int co = jb >> 8;
    #pragma unroll
    for (int i = 0; i < 4; i += 2) {
        int jg4  = jb + jg*4 + i;
        int ci   = (jg4 & 255) >> 1;
        float tbg = tb[jg4], tbb_ = tb[jg4+1];
        #pragma unroll
        for (int nn = 0; nn < 4; nn++) {
            int n = ng*4 + nn;
            g_gam[layer][((size_t)n*128 + co)*128 + ci] = acc[i][nn]  * se + tbg;
            g_bet[layer][((size_t)n*128 + co)*128 + ci] = acc[i+1][nn]* se + tbb_;
        }
    }
}

// ---------------- fragment builder: coalesced uint4 stores ----------------
__global__ __launch_bounds__(256)
void wfrag_build_kernel(const float* __restrict__ Wt, int layer)
{
    const int chunk = blockIdx.x;
    const int n     = blockIdx.y;
    const int tid   = threadIdx.x;
    const float swm = 1.0f/24.0f;

    const float* gam = g_gam[layer] + (size_t)n * CH * CH;
    const float* bet = g_bet[layer] + (size_t)n * CH * CH;
    uint32_t* outh = g_wfh[layer] + (size_t)n * WFRAG_PER_N + chunk * 4096;
    uint32_t* outl = g_wfl[layer] + (size_t)n * WFRAG_PER_N + chunk * 4096;

    #pragma unroll
    for (int it = 0; it < 4; it++) {
        int wbase = it*1024 + tid*4;
        uint32_t hq[4], lq[4];
        #pragma unroll
        for (int q = 0; q < 4; q++) {
            int w = wbase + q;
            int reg   = w & 3;
            int ln    = (w >> 2) & 31;
            int m16   = (w >> 7) & 7;
            int kstep = w >> 10;
            int row16 = ((ln >> 2) & 7) | ((reg & 1) << 3);
            int co    = m16*16 + row16;
            int kk16  = ((ln & 3) << 1) | ((reg >> 1) << 3);
            int k0    = chunk*64 + kstep*16 + kk16;
            int k1    = k0 + 1;
            int ci0 = k0/9, k90 = k0 - 9*ci0;
            int ci1 = k1/9, k91 = k1 - 9*ci1;
            float w0 = fmaf(Wt[(co*128 + ci0)*9 + k90], gam[co*128 + ci0], bet[co*128 + ci0]) * swm;
            float w1 = fmaf(Wt[(co*128 + ci1)*9 + k91], gam[co*128 + ci1], bet[co*128 + ci1]) * swm;
            __nv_bfloat16 h0 = __float2bfloat16(w0);
            __nv_bfloat16 h1 = __float2bfloat16(w1);
            __nv_bfloat16 l0 = __float2bfloat16(w0 - __bfloat162float(h0));
            __nv_bfloat16 l1 = __float2bfloat16(w1 - __bfloat162float(h1));
            hq[q] = (uint32_t)__bfloat16_as_ushort(h0) | ((uint32_t)__bfloat16_as_ushort(h1) << 16);
            lq[q] = (uint32_t)__bfloat16_as_ushort(l0) | ((uint32_t)__bfloat16_as_ushort(l1) << 16);
        }
        *(uint4*)(outh + wbase) = make_uint4(hq[0], hq[1], hq[2], hq[3]);
        *(uint4*)(outl + wbase) = make_uint4(lq[0], lq[1], lq[2], lq[3]);
    }
}

// ---------------- adain-1 affine params (replaces full adain pass) --------
__global__ void adain_params_kernel()
{
    const int n  = blockIdx.x;
    const int c  = threadIdx.x;
    const int nc = n*128 + c;
    float mu  = g_stats[0][nc*2]   * (1.f/4096.f);
    float var = g_stats[0][nc*2+1] * (1.f/4096.f) - mu*mu;
    var = fmaxf(var, 0.f);
    float inv = rsqrtf(var + 1e-5f);
    float g = g_adg[0][nc] * inv;
    float b = g_adb[0][nc] - g * mu;
    g_affp[nc*2]   = g;
    g_affp[nc*2+1] = b;
}

// ---------------- helpers ----------------
__device__ __forceinline__ uint32_t split_pack(float v) {
    uint32_t b = __float_as_uint(v);
    uint32_t hbits = b & 0xFFFF0000u;
    float l = v - __uint_as_float(hbits);
    uint16_t lb = __bfloat16_as_ushort(__float2bfloat16(l));
    return (b >> 16) | ((uint32_t)lb << 16);
}

// ---------------- mma.sync conv: fused affine+split B gather --------------
#define B_WORDS 2048
#define SM_BH 0
#define SM_BL (B_WORDS)
#define SM_NZ (2*B_WORDS)
#define SM_BI (SM_NZ + 64)
#define SM_NW (SM_BI + 128)
#define SM_AFF (SM_NW + 128)                 // 256 floats (g,b per ci)
#define SM_TAB (SM_AFF + 256)
#define SMEM_WORDS (SM_TAB + KTOT)
#define SMEM_BYTES (SMEM_WORDS * 4)

__device__ __forceinline__ void mma16816(float* d, const uint4& a, uint32_t b0, uint32_t b1) {
    asm volatile(
        "mma.sync.aligned.m16n8k16.row.col.f32.bf16.bf16.f32 "
        "{%0,%1,%2,%3}, {%4,%5,%6,%7}, {%8,%9}, {%0,%1,%2,%3};"
        : "+f"(d[0]), "+f"(d[1]), "+f"(d[2]), "+f"(d[3])
        : "r"(a.x), "r"(a.y), "r"(a.z), "r"(a.w), "r"(b0), "r"(b1));
}

// gather fp32 source, apply per-ci affine, bf16-split, pack
__device__ __forceinline__ void prefetch_b(const uint32_t* __restrict__ sm_tab,
                                           const float* __restrict__ s_aff,
                                           const float* __restrict__ base,
                                           uint32_t vmask, int kc, int bkp0,
                                           uint32_t* bPre)
{
    #pragma unroll
    for (int j = 0; j < 16; j++) {
        int kp = bkp0 + 2*j;
        int k0 = kc + kp*2;
        uint2 t = *(const uint2*)&sm_tab[k0];
        float z0 = 0.f, z1 = 0.f;
        if ((vmask >> (t.x >> 27)) & 1u) {
            int ci = (t.x >> 20) & 0x7F;
            z0 = fmaf(s_aff[ci*2], base[t.x & 0xFFFFFu], s_aff[ci*2+1]);
        }
        if ((vmask >> (t.y >> 27)) & 1u) {
            int ci = (t.y >> 20) & 0x7F;
            z1 = fmaf(s_aff[ci*2], base[t.y & 0xFFFFFu], s_aff[ci*2+1]);
        }
        bPre[2*j]   = split_pack(z0);
        bPre[2*j+1] = split_pack(z1);
    }
}

__global__ __launch_bounds__(128, 2)
void conv_mma_kernel(int layer, const float* __restrict__ src, const float* __restrict__ aff,
                     const float* __restrict__ noise, const float* __restrict__ nzw)
{
    extern __shared__ uint32_t sm[];
    float* s_noise = (float*)(sm + SM_NZ);
    float* s_bias  = (float*)(sm + SM_BI);
    float* s_nw    = (float*)(sm + SM_NW);
    float* s_aff   = (float*)(sm + SM_AFF);

    const int tid  = threadIdx.x;
    const int lane = tid & 31;
    const int mrow = tid >> 5;
    const int tile = blockIdx.x;
    const int n    = blockIdx.y;

    const float*    xn  = src + (size_t)n * CH * HWPX;
    const uint32_t* wfh = g_wfh[layer] + (size_t)n * WFRAG_PER_N;
    const uint32_t* wfl = g_wfl[layer] + (size_t)n * WFRAG_PER_N;

    if (tid < 64) s_noise[tid] = noise[(size_t)n*HWPX + tile*64 + tid];
    s_bias[tid] = g_bias[layer][n*128 + tid];
    s_nw[tid]   = nzw[tid] * 0.125f;
    // affine table: identity for layer 0, fused adain-1 for layer 1
    #pragma unroll
    for (int i = tid; i < 256; i += 128)
        s_aff[i] = aff ? aff[n*256 + i] : ((i & 1) ? 0.f : 1.f);
    for (int k = tid; k < KTOT; k += 128) {
        int ci = k / 9, r = k - 9*ci, ky = r / 3, kx = r - 3*ky;
        sm[SM_TAB + k] = ((uint32_t)(ky*3 + kx) << 27) | ((uint32_t)ci << 20)
                       | (uint32_t)(ci*HWPX + ky*64 + kx);
    }

    const int bp   = tid & 63;
    const int bkp0 = tid >> 6;
    const int by   = tile;
    const int bx   = bp;
    const float* gbase = xn + (by - 1)*64 + (bx - 1);
    uint32_t vmask = 0;
    #pragma unroll
    for (int kyx = 0; kyx < 9; kyx++) {
        int ky = kyx / 3, kx = kyx - 3*ky;
        int ya = by + ky - 1, xa = bx + kx - 1;
        if ((unsigned)ya < 64u && (unsigned)xa < 64u) vmask |= (1u << kyx);
    }

    __syncthreads();

    uint32_t bPre[32];
    prefetch_b(sm + SM_TAB, s_aff, gbase, vmask, 0, bkp0, bPre);

    float acc[2][8][4] = {};
    const int mt0 = mrow*2, mt1 = mrow*2 + 1;

    for (int kci = 0; kci < NCHUNK; kci++) {
        const uint32_t* ah = wfh + kci*4096;
        const uint32_t* al = wfl + kci*4096;
        uint4 Ah[4][2], Al[4][2];
        #pragma unroll
        for (int ks = 0; ks < 4; ks++) {
            Ah[ks][0] = *(const uint4*)&ah[(ks*8 + mt0)*128 + lane*4];
            Ah[ks][1] = *(const uint4*)&ah[(ks*8 + mt1)*128 + lane*4];
            Al[ks][0] = *(const uint4*)&al[(ks*8 + mt0)*128 + lane*4];
            Al[ks][1] = *(const uint4*)&al[(ks*8 + mt1)*128 + lane*4];
        }

        __syncthreads();

        #pragma unroll
        for (int j = 0; j < 16; j++) {
            int kp = bkp0 + 2*j;
            uint32_t u0 = bPre[2*j], u1 = bPre[2*j+1];
            uint32_t hp = __byte_perm(u0, u1, 0x5410);
            uint32_t lp = __byte_perm(u0, u1, 0x7632);
            int kstep = kp >> 3;
            int kk16  = (kp*2) & 15;
            int n8    = bp >> 3;
            int ln    = ((bp & 7) << 2) + ((kk16 & 7) >> 1);
            int reg   = kk16 >> 3;
            int w = (((kstep << 3) + n8)*32 + ln)*2 + reg;
            sm[SM_BH + w] = hp;
            sm[SM_BL + w] = lp;
        }
        __syncthreads();

        if (kci + 1 < NCHUNK)
            prefetch_b(sm + SM_TAB, s_aff, gbase, vmask, (kci + 1)*KC, bkp0, bPre);

        const uint32_t* BH = sm + SM_BH;
        const uint32_t* BL = sm + SM_BL;
        #pragma unroll
        for (int ks = 0; ks < 4; ks++) {
            #pragma unroll
            for (int j = 0; j < 8; j++) {
                int bidx = (((ks << 3) + j)*32 + lane)*2;
                uint2 bh = *(const uint2*)&BH[bidx];
                uint2 bl = *(const uint2*)&BL[bidx];
                mma16816(acc[0][j], Ah[ks][0], bh.x, bh.y);
                mma16816(acc[1][j], Ah[ks][1], bh.x, bh.y);
                mma16816(acc[0][j], Al[ks][0], bh.x, bh.y);
                mma16816(acc[1][j], Al[ks][1], bh.x, bh.y);
                mma16816(acc[0][j], Ah[ks][0], bl.x, bl.y);
                mma16816(acc[1][j], Ah[ks][1], bl.x, bl.y);
            }
        }
    }

    // ---- epilogue ----
    const int g4 = lane >> 2;
    const int q  = lane & 3;
    float psum[2][2] = {}, psq[2][2] = {};
    #pragma unroll
    for (int m = 0; m < 2; m++) {
        int coA = (mrow*2 + m)*16 + g4;
        int coB = coA + 8;
        float biA = s_bias[coA], nwA = s_nw[coA];
        float biB = s_bias[coB], nwB = s_nw[coB];
        float* rowA = g_y[layer] + ((size_t)(n*128 + coA))*HWPX + tile*64;
        float* rowB = g_y[layer] + ((size_t)(n*128 + coB))*HWPX + tile*64;
        #pragma unroll
        for (int j = 0; j < 8; j++) {
            int px = j*8 + q*2;
            float nz0 = s_noise[px], nz1 = s_noise[px+1];
            float a0 = acc[m][j][0] + biA + nwA*nz0;
            float a1 = acc[m][j][1] + biA + nwA*nz1;
            float b0 = acc[m][j][2] + biB + nwB*nz0;
            float b1 = acc[m][j][3] + biB + nwB*nz1;
            a0 = (a0 > 0.f) ? a0 : 0.2f*a0;
            a1 = (a1 > 0.f) ? a1 : 0.2f*a1;
            b0 = (b0 > 0.f) ? b0 : 0.2f*b0;
            b1 = (b1 > 0.f) ? b1 : 0.2f*b1;
            *(float2*)(rowA + px) = make_float2(a0, a1);
            *(float2*)(rowB + px) = make_float2(b0, b1);
            psum[m][0] += a0 + a1; psq[m][0] += a0*a0 + a1*a1;
            psum[m][1] += b0 + b1; psq[m][1] += b0*b0 + b1*b1;
        }
    }
    #pragma unroll
    for (int off = 1; off < 4; off <<= 1) {
        #pragma unroll
        for (int m = 0; m < 2; m++)
            #pragma unroll
            for (int h = 0; h < 2; h++) {
                psum[m][h] += __shfl_xor_sync(0xffffffffu, psum[m][h], off);
                psq [m][h] += __shfl_xor_sync(0xffffffffu, psq [m][h], off);
            }
    }
    if (q == 0) {
        #pragma unroll
        for (int m = 0; m < 2; m++)
            #pragma unroll
            for (int h = 0; h < 2; h++) {
                int co = (mrow*2 + m)*16 + g4 + h*8;
                atomicAdd(&g_stats[layer][(n*128+co)*2 + 0], psum[m][h]);
                atomicAdd(&g_stats[layer][(n*128+co)*2 + 1], psq[m][h]);
            }
    }
}

// ---------------- final AdaIN (layer 2 -> output) -------------------------
__global__ void adain_final_kernel(float* __restrict__ dout)
{
    const int nc = blockIdx.y;
    const int i4 = blockIdx.x * blockDim.x + threadIdx.x;
    float mu  = g_stats[1][nc*2]   * (1.f/4096.f);
    float var = g_stats[1][nc*2+1] * (1.f/4096.f) - mu*mu;
    var = fmaxf(var, 0.f);
    float inv = rsqrtf(var + 1e-5f);
    float g = g_adg[1][nc] * inv;
    float b = g_adb[1][nc] - g * mu;
    const float4* yin = (const float4*)(g_y[1] + (size_t)nc * HWPX);
    float4 v = yin[i4];
    float4 o;
    o.x = fmaf(g, v.x, b); o.y = fmaf(g, v.y, b);
    o.z = fmaf(g, v.z, b); o.w = fmaf(g, v.w, b);
    ((float4*)(dout + (size_t)nc * HWPX))[i4] = o;
}

// ---------------- launch ----------------
extern "C" void kernel_launch(void* const* d_in, const int* in_sizes, int n_in,
                              void* d_out, int out_size)
{
    const float* x     = (const float*)d_in[0];
    const float* style = (const float*)d_in[1];
    const float* noise = (const float*)d_in[2];
    const float* task  = (const float*)d_in[3];
    const float* W1    = (const float*)d_in[4];
    const float* b1    = (const float*)d_in[5];
    const float* t1w   = (const float*)d_in[6];
    const float* t1b   = (const float*)d_in[7];
    const float* tb1w  = (const float*)d_in[8];
    const float* tb1b  = (const float*)d_in[9];
    const float* nz1   = (const float*)d_in[10];
    const float* ad1w  = (const float*)d_in[11];
    const float* ad1b  = (const float*)d_in[12];
    const float* W2    = (const float*)d_in[13];
    const float* b2    = (const float*)d_in[14];
    const float* t2w   = (const float*)d_in[15];
    const float* t2b   = (const float*)d_in[16];
    const float* tb2w  = (const float*)d_in[17];
    const float* tb2b  = (const float*)d_in[18];
    const float* nz2   = (const float*)d_in[19];
    const float* ad2w  = (const float*)d_in[20];
    const float* ad2b  = (const float*)d_in[21];
    float* out = (float*)d_out;

    static cudaStream_t s2 = nullptr;
    static cudaEvent_t ev_root = nullptr, ev_pre = nullptr, ev_l2 = nullptr;
    static float* d_y0 = nullptr;
    static float* d_affp = nullptr;
    if (s2 == nullptr) {
        cudaStreamCreateWithFlags(&s2, cudaStreamNonBlocking);
        cudaEventCreateWithFlags(&ev_root, cudaEventDisableTiming);
        cudaEventCreateWithFlags(&ev_pre,  cudaEventDisableTiming);
        cudaEventCreateWithFlags(&ev_l2,   cudaEventDisableTiming);
        cudaFuncSetAttribute(conv_mma_kernel,
                             cudaFuncAttributeMaxDynamicSharedMemorySize, SMEM_BYTES);
        cudaGetSymbolAddress((void**)&d_y0, g_y);
        cudaGetSymbolAddress((void**)&d_affp, g_affp);
    }

    cudaEventRecord(ev_root, 0);
    cudaStreamWaitEvent(s2, ev_root, 0);

    // s2: per-sample vectors + layer-2 producers
    modvec_kernel<<<32, 128, 0, s2>>>(task, style, b1, tb1w, tb1b, ad1w, ad1b,
                                      b2, tb2w, tb2b, ad2w, ad2b);
    cudaEventRecord(ev_pre, s2);
    gemm_wmod_kernel<<<512, 128, 0, s2>>>(task, t2w, t2b, 1);
    wfrag_build_kernel<<<dim3(NCHUNK, N_SMP), 256, 0, s2>>>(W2, 1);
    cudaEventRecord(ev_l2, s2);

    // main: layer-1 producers -> conv1 -> params -> conv2 -> final adain
    gemm_wmod_kernel<<<512, 128>>>(task, t1w, t1b, 0);
    wfrag_build_kernel<<<dim3(NCHUNK, N_SMP), 256>>>(W1, 0);
    cudaStreamWaitEvent(0, ev_pre, 0);
    conv_mma_kernel<<<dim3(64, N_SMP), 128, SMEM_BYTES>>>(0, x, nullptr, noise, nz1);
    adain_params_kernel<<<32, 128>>>();
    cudaStreamWaitEvent(0, ev_l2, 0);
    conv_mma_kernel<<<dim3(64, N_SMP), 128, SMEM_BYTES>>>(1, d_y0, d_affp, noise, nz2);
    adain_final_kernel<<<dim3(4, 4096), 256>>>(out);
}

// round 16
// speedup vs baseline: 1.2821x; 1.2821x over previous
#include <cuda_runtime.h>
#include <cuda_bf16.h>
#include <math.h>
#include <stdint.h>

#define N_SMP 32
#define CH    128
#define HWPX  4096
#define KTOT  1152
#define KC    64
#define NCHUNK 18
#define WFRAG_PER_N 73728   // u32 per sample: 18 chunk * 4 kstep * 8 m16 * 32 lane * 4 reg

// ---------------- device scratch (layer-indexed where cross-stream) -------
__device__ uint32_t g_wfh[2][N_SMP * WFRAG_PER_N];
__device__ uint32_t g_wfl[2][N_SMP * WFRAG_PER_N];
__device__ float    g_gam[2][N_SMP * CH * CH];
__device__ float    g_bet[2][N_SMP * CH * CH];
__device__ uint32_t g_xp[N_SMP * CH * HWPX];     // x as (hi|lo<<16) bf16 pair
__device__ float g_y[N_SMP * CH * HWPX];
__device__ float g_stats[2][N_SMP * CH * 2];
__device__ float g_bias[2][N_SMP * CH];
__device__ float g_adg[2][N_SMP * CH];
__device__ float g_adb[2][N_SMP * CH];

// ---------------- small per-sample vectors ----------------
__global__ void modvec_kernel(const float* __restrict__ task, const float* __restrict__ style,
    const float* __restrict__ b1, const float* __restrict__ tb1w, const float* __restrict__ tb1b,
    const float* __restrict__ ad1w, const float* __restrict__ ad1b,
    const float* __restrict__ b2, const float* __restrict__ tb2w, const float* __restrict__ tb2b,
    const float* __restrict__ ad2w, const float* __restrict__ ad2b)
{
    __shared__ float ts[512], ss[512];
    const int n = blockIdx.x;
    const int co = threadIdx.x;
    for (int k = co; k < 512; k += 128) { ts[k] = task[n*512+k]; ss[k] = style[n*512+k]; }
    __syncthreads();
    float a0=0.f,a1=0.f,a2=0.f,a3=0.f,a4=0.f,a5=0.f;
    for (int k = 0; k < 512; k++) {
        float t = ts[k], s = ss[k];
        a0 = fmaf(tb1w[co*512+k],       t, a0);
        a1 = fmaf(ad1w[co*512+k],       s, a1);
        a2 = fmaf(ad1w[(co+128)*512+k], s, a2);
        a3 = fmaf(tb2w[co*512+k],       t, a3);
        a4 = fmaf(ad2w[co*512+k],       s, a4);
        a5 = fmaf(ad2w[(co+128)*512+k], s, a5);
    }
    const float se = 0.0625f;
    g_bias[0][n*128+co] = b1[co] + a0*se + tb1b[co];
    g_adg [0][n*128+co] = a1*se + ad1b[co];
    g_adb [0][n*128+co] = a2*se + ad1b[co+128];
    g_bias[1][n*128+co] = b2[co] + a3*se + tb2b[co];
    g_adg [1][n*128+co] = a4*se + ad2b[co];
    g_adb [1][n*128+co] = a5*se + ad2b[co+128];
}

// ---------------- gamma/beta GEMM -> coalesced gamma/beta stores ---------
#define GB_JT 64
#define GB_KC 16
__global__ __launch_bounds__(128)
void gemm_wmod_kernel(const float* __restrict__ task, const float* __restrict__ tw,
                      const float* __restrict__ tb, int layer)
{
    __shared__ float As[GB_KC][GB_JT];
    __shared__ float Bs[GB_KC][32];
    const int tid = threadIdx.x;
    const int jb  = blockIdx.x * GB_JT;
    const int jg  = tid & 15;
    const int ng  = tid >> 4;

    if (blockIdx.x < 64) g_stats[layer][blockIdx.x * 128 + tid] = 0.f;

    float acc[4][4] = {};

    for (int k0 = 0; k0 < 512; k0 += GB_KC) {
        #pragma unroll
        for (int t = 0; t < 2; t++) {
            int li  = tid*2 + t;
            int row = li >> 2;
            int kq  = (li & 3) * 4;
            float4 v = *(const float4*)(tw + (size_t)(jb + row)*512 + k0 + kq);
            As[kq+0][row] = v.x; As[kq+1][row] = v.y; As[kq+2][row] = v.z; As[kq+3][row] = v.w;
        }
        {
            int nn = tid >> 2;
            int kq = (tid & 3) * 4;
            float4 v = *(const float4*)(task + (size_t)nn*512 + k0 + kq);
            Bs[kq+0][nn] = v.x; Bs[kq+1][nn] = v.y; Bs[kq+2][nn] = v.z; Bs[kq+3][nn] = v.w;
        }
        __syncthreads();
        #pragma unroll
        for (int k = 0; k < GB_KC; k++) {
            float4 a = *(const float4*)&As[k][jg*4];
            float4 b = *(const float4*)&Bs[k][ng*4];
            float av[4] = {a.x,a.y,a.z,a.w};
            float bv[4] = {b.x,b.y,b.z,b.w};
            #pragma unroll
            for (int i = 0; i < 4; i++)
                #pragma unroll
                for (int j = 0; j < 4; j++)
                    acc[i][j] = fmaf(av[i], bv[j], acc[i][j]);
        }
        __syncthreads();
    }

    const float se = 0.0625f;
    const int co = jb >> 8;
    #pragma unroll
    for (int i = 0; i < 4; i += 2) {
        int jg4  = jb + jg*4 + i;
        int ci   = (jg4 & 255) >> 1;
        float tbg = tb[jg4], tbb_ = tb[jg4+1];
        #pragma unroll
        for (int nn = 0; nn < 4; nn++) {
            int n = ng*4 + nn;
            g_gam[layer][((size_t)n*128 + co)*128 + ci] = acc[i][nn]  * se + tbg;
            g_bet[layer][((size_t)n*128 + co)*128 + ci] = acc[i+1][nn]* se + tbb_;
        }
    }
}

// ---------------- fragment builder: coalesced uint4 stores ----------------
__global__ __launch_bounds__(256)
void wfrag_build_kernel(const float* __restrict__ Wt, int layer)
{
    const int chunk = blockIdx.x;
    const int n     = blockIdx.y;
    const int tid   = threadIdx.x;
    const float swm = 1.0f/24.0f;

    const float* gam = g_gam[layer] + (size_t)n * CH * CH;
    const float* bet = g_bet[layer] + (size_t)n * CH * CH;
    uint32_t* outh = g_wfh[layer] + (size_t)n * WFRAG_PER_N + chunk * 4096;
    uint32_t* outl = g_wfl[layer] + (size_t)n * WFRAG_PER_N + chunk * 4096;

    #pragma unroll
    for (int it = 0; it < 4; it++) {
        int wbase = it*1024 + tid*4;
        uint32_t hq[4], lq[4];
        #pragma unroll
        for (int q = 0; q < 4; q++) {
            int w = wbase + q;
            int reg   = w & 3;
            int ln    = (w >> 2) & 31;
            int m16   = (w >> 7) & 7;
            int kstep = w >> 10;
            int row16 = ((ln >> 2) & 7) | ((reg & 1) << 3);
            int co    = m16*16 + row16;
            int kk16  = ((ln & 3) << 1) | ((reg >> 1) << 3);
            int k0    = chunk*64 + kstep*16 + kk16;
            int k1    = k0 + 1;
            int ci0 = k0/9, k90 = k0 - 9*ci0;
            int ci1 = k1/9, k91 = k1 - 9*ci1;
            float w0 = fmaf(Wt[(co*128 + ci0)*9 + k90], gam[co*128 + ci0], bet[co*128 + ci0]) * swm;
            float w1 = fmaf(Wt[(co*128 + ci1)*9 + k91], gam[co*128 + ci1], bet[co*128 + ci1]) * swm;
            __nv_bfloat16 h0 = __float2bfloat16(w0);
            __nv_bfloat16 h1 = __float2bfloat16(w1);
            __nv_bfloat16 l0 = __float2bfloat16(w0 - __bfloat162float(h0));
            __nv_bfloat16 l1 = __float2bfloat16(w1 - __bfloat162float(h1));
            hq[q] = (uint32_t)__bfloat16_as_ushort(h0) | ((uint32_t)__bfloat16_as_ushort(h1) << 16);
            lq[q] = (uint32_t)__bfloat16_as_ushort(l0) | ((uint32_t)__bfloat16_as_ushort(l1) << 16);
        }
        *(uint4*)(outh + wbase) = make_uint4(hq[0], hq[1], hq[2], hq[3]);
        *(uint4*)(outl + wbase) = make_uint4(lq[0], lq[1], lq[2], lq[3]);
    }
}

// ---------------- x split: f32 -> (bf16 hi | bf16 lo << 16) ----------------
__device__ __forceinline__ uint32_t split_pack(float v) {
    uint32_t b = __float_as_uint(v);
    uint32_t hbits = b & 0xFFFF0000u;
    float l = v - __uint_as_float(hbits);
    uint16_t lb = __bfloat16_as_ushort(__float2bfloat16(l));
    return (b >> 16) | ((uint32_t)lb << 16);
}

__global__ void split_x_kernel(const float* __restrict__ x) {
    int i = blockIdx.x * blockDim.x + threadIdx.x;
    float4 v = ((const float4*)x)[i];
    uint4 o;
    o.x = split_pack(v.x); o.y = split_pack(v.y);
    o.z = split_pack(v.z); o.w = split_pack(v.w);
    ((uint4*)g_xp)[i] = o;
}

// ---------------- mma.sync conv: 128 threads, 128co x 64px, 2 CTAs/SM -----
#define B_WORDS 2048
#define SM_BH 0
#define SM_BL (B_WORDS)
#define SM_NZ (2*B_WORDS)
#define SM_BI (SM_NZ + 64)
#define SM_NW (SM_BI + 128)
#define SM_TAB (SM_NW + 128)
#define SMEM_WORDS (SM_TAB + KTOT)
#define SMEM_BYTES (SMEM_WORDS * 4)

__device__ __forceinline__ void mma16816(float* d, const uint4& a, uint32_t b0, uint32_t b1) {
    asm volatile(
        "mma.sync.aligned.m16n8k16.row.col.f32.bf16.bf16.f32 "
        "{%0,%1,%2,%3}, {%4,%5,%6,%7}, {%8,%9}, {%0,%1,%2,%3};"
        : "+f"(d[0]), "+f"(d[1]), "+f"(d[2]), "+f"(d[3])
        : "r"(a.x), "r"(a.y), "r"(a.z), "r"(a.w), "r"(b0), "r"(b1));
}

__device__ __forceinline__ void prefetch_b(const uint32_t* __restrict__ sm_tab,
                                           const uint32_t* __restrict__ base,
                                           uint32_t vmask, int kc, int bkp0,
                                           uint32_t* bPre)
{
    #pragma unroll
    for (int j = 0; j < 16; j++) {
        int kp = bkp0 + 2*j;
        int k0 = kc + kp*2;
        uint2 t = *(const uint2*)&sm_tab[k0];
        uint32_t p0 = (vmask >> (t.x >> 24)) & 1u;
        uint32_t p1 = (vmask >> (t.y >> 24)) & 1u;
        bPre[2*j]   = p0 ? base[t.x & 0xFFFFFFu] : 0u;
        bPre[2*j+1] = p1 ? base[t.y & 0xFFFFFFu] : 0u;
    }
}

__global__ __launch_bounds__(128, 2)
void conv_mma_kernel(int layer, const float* __restrict__ noise, const float* __restrict__ nzw)
{
    extern __shared__ uint32_t sm[];
    float* s_noise = (float*)(sm + SM_NZ);
    float* s_bias  = (float*)(sm + SM_BI);
    float* s_nw    = (float*)(sm + SM_NW);

    const int tid  = threadIdx.x;
    const int lane = tid & 31;
    const int mrow = tid >> 5;
    const int tile = blockIdx.x;
    const int n    = blockIdx.y;

    const uint32_t* xp  = g_xp + (size_t)n * CH * HWPX;
    const uint32_t* wfh = g_wfh[layer] + (size_t)n * WFRAG_PER_N;
    const uint32_t* wfl = g_wfl[layer] + (size_t)n * WFRAG_PER_N;

    if (tid < 64) s_noise[tid] = noise[(size_t)n*HWPX + tile*64 + tid];
    s_bias[tid] = g_bias[layer][n*128 + tid];
    s_nw[tid]   = nzw[tid] * 0.125f;
    for (int k = tid; k < KTOT; k += 128) {
        int ci = k / 9, r = k - 9*ci, ky = r / 3, kx = r - 3*ky;
        sm[SM_TAB + k] = ((uint32_t)(ky*3 + kx) << 24) | (uint32_t)(ci*HWPX + ky*64 + kx);
    }

    const int bp   = tid & 63;
    const int bkp0 = tid >> 6;
    const int by   = tile;
    const int bx   = bp;
    const uint32_t* gbase = xp + (by - 1)*64 + (bx - 1);
    uint32_t vmask = 0;
    #pragma unroll
    for (int kyx = 0; kyx < 9; kyx++) {
        int ky = kyx / 3, kx = kyx - 3*ky;
        int ya = by + ky - 1, xa = bx + kx - 1;
        if ((unsigned)ya < 64u && (unsigned)xa < 64u) vmask |= (1u << kyx);
    }

    __syncthreads();

    uint32_t bPre[32];
    prefetch_b(sm + SM_TAB, gbase, vmask, 0, bkp0, bPre);

    float acc[2][8][4] = {};
    const int mt0 = mrow*2, mt1 = mrow*2 + 1;

    for (int kci = 0; kci < NCHUNK; kci++) {
        const uint32_t* ah = wfh + kci*4096;
        const uint32_t* al = wfl + kci*4096;
        uint4 Ah[4][2], Al[4][2];
        #pragma unroll
        for (int ks = 0; ks < 4; ks++) {
            Ah[ks][0] = *(const uint4*)&ah[(ks*8 + mt0)*128 + lane*4];
            Ah[ks][1] = *(const uint4*)&ah[(ks*8 + mt1)*128 + lane*4];
            Al[ks][0] = *(const uint4*)&al[(ks*8 + mt0)*128 + lane*4];
            Al[ks][1] = *(const uint4*)&al[(ks*8 + mt1)*128 + lane*4];
        }

        __syncthreads();

        #pragma unroll
        for (int j = 0; j < 16; j++) {
            int kp = bkp0 + 2*j;
            uint32_t u0 = bPre[2*j], u1 = bPre[2*j+1];
            uint32_t hp = __byte_perm(u0, u1, 0x5410);
            uint32_t lp = __byte_perm(u0, u1, 0x7632);
            int kstep = kp >> 3;
            int kk16  = (kp*2) & 15;
            int n8    = bp >> 3;
            int ln    = ((bp & 7) << 2) + ((kk16 & 7) >> 1);
            int reg   = kk16 >> 3;
            int w = (((kstep << 3) + n8)*32 + ln)*2 + reg;
            sm[SM_BH + w] = hp;
            sm[SM_BL + w] = lp;
        }
        __syncthreads();

        // prefetch next chunk's B gather (skipped on last chunk — values unused)
        if (kci + 1 < NCHUNK)
            prefetch_b(sm + SM_TAB, gbase, vmask, (kci + 1)*KC, bkp0, bPre);

        const uint32_t* BH = sm + SM_BH;
        const uint32_t* BL = sm + SM_BL;
        #pragma unroll
        for (int ks = 0; ks < 4; ks++) {
            #pragma unroll
            for (int j = 0; j < 8; j++) {
                int bidx = (((ks << 3) + j)*32 + lane)*2;
                uint2 bh = *(const uint2*)&BH[bidx];
                uint2 bl = *(const uint2*)&BL[bidx];
                mma16816(acc[0][j], Ah[ks][0], bh.x, bh.y);
                mma16816(acc[1][j], Ah[ks][1], bh.x, bh.y);
                mma16816(acc[0][j], Al[ks][0], bh.x, bh.y);
                mma16816(acc[1][j], Al[ks][1], bh.x, bh.y);
                mma16816(acc[0][j], Ah[ks][0], bl.x, bl.y);
                mma16816(acc[1][j], Ah[ks][1], bl.x, bl.y);
            }
        }
    }

    // ---- epilogue ----
    const int g4 = lane >> 2;
    const int q  = lane & 3;
    float psum[2][2] = {}, psq[2][2] = {};
    #pragma unroll
    for (int m = 0; m < 2; m++) {
        int coA = (mrow*2 + m)*16 + g4;
        int coB = coA + 8;
        float biA = s_bias[coA], nwA = s_nw[coA];
        float biB = s_bias[coB], nwB = s_nw[coB];
        float* rowA = g_y + ((size_t)(n*128 + coA))*HWPX + tile*64;
        float* rowB = g_y + ((size_t)(n*128 + coB))*HWPX + tile*64;
        #pragma unroll
        for (int j = 0; j < 8; j++) {
            int px = j*8 + q*2;
            float nz0 = s_noise[px], nz1 = s_noise[px+1];
            float a0 = acc[m][j][0] + biA + nwA*nz0;
            float a1 = acc[m][j][1] + biA + nwA*nz1;
            float b0 = acc[m][j][2] + biB + nwB*nz0;
            float b1 = acc[m][j][3] + biB + nwB*nz1;
            a0 = (a0 > 0.f) ? a0 : 0.2f*a0;
            a1 = (a1 > 0.f) ? a1 : 0.2f*a1;
            b0 = (b0 > 0.f) ? b0 : 0.2f*b0;
            b1 = (b1 > 0.f) ? b1 : 0.2f*b1;
            *(float2*)(rowA + px) = make_float2(a0, a1);
            *(float2*)(rowB + px) = make_float2(b0, b1);
            psum[m][0] += a0 + a1; psq[m][0] += a0*a0 + a1*a1;
            psum[m][1] += b0 + b1; psq[m][1] += b0*b0 + b1*b1;
        }
    }
    #pragma unroll
    for (int off = 1; off < 4; off <<= 1) {
        #pragma unroll
        for (int m = 0; m < 2; m++)
            #pragma unroll
            for (int h = 0; h < 2; h++) {
                psum[m][h] += __shfl_xor_sync(0xffffffffu, psum[m][h], off);
                psq [m][h] += __shfl_xor_sync(0xffffffffu, psq [m][h], off);
            }
    }
    if (q == 0) {
        #pragma unroll
        for (int m = 0; m < 2; m++)
            #pragma unroll
            for (int h = 0; h < 2; h++) {
                int co = (mrow*2 + m)*16 + g4 + h*8;
                atomicAdd(&g_stats[layer][(n*128+co)*2 + 0], psum[m][h]);
                atomicAdd(&g_stats[layer][(n*128+co)*2 + 1], psq[m][h]);
            }
    }
}

// ---------------- AdaIN (fuses bf16 split for next conv on layer 1) -------
__global__ void adain_kernel(int layer, int to_xp, float* __restrict__ dout)
{
    const int nc = blockIdx.y;
    const int i4 = blockIdx.x * blockDim.x + threadIdx.x;
    float mu  = g_stats[layer][nc*2]   * (1.f/4096.f);
    float var = g_stats[layer][nc*2+1] * (1.f/4096.f) - mu*mu;
    var = fmaxf(var, 0.f);
    float inv = rsqrtf(var + 1e-5f);
    float g = g_adg[layer][nc] * inv;
    float b = g_adb[layer][nc] - g * mu;
    const float4* yin = (const float4*)(g_y + (size_t)nc * HWPX);
    float4 v = yin[i4];
    float4 o;
    o.x = fmaf(g, v.x, b); o.y = fmaf(g, v.y, b);
    o.z = fmaf(g, v.z, b); o.w = fmaf(g, v.w, b);
    if (to_xp) {
        uint4 p;
        p.x = split_pack(o.x); p.y = split_pack(o.y);
        p.z = split_pack(o.z); p.w = split_pack(o.w);
        ((uint4*)(g_xp + (size_t)nc * HWPX))[i4] = p;
    } else {
        ((float4*)(dout + (size_t)nc * HWPX))[i4] = o;
    }
}

// ---------------- launch ----------------
extern "C" void kernel_launch(void* const* d_in, const int* in_sizes, int n_in,
                              void* d_out, int out_size)
{
    const float* x     = (const float*)d_in[0];
    const float* style = (const float*)d_in[1];
    const float* noise = (const float*)d_in[2];
    const float* task  = (const float*)d_in[3];
    const float* W1    = (const float*)d_in[4];
    const float* b1    = (const float*)d_in[5];
    const float* t1w   = (const float*)d_in[6];
    const float* t1b   = (const float*)d_in[7];
    const float* tb1w  = (const float*)d_in[8];
    const float* tb1b  = (const float*)d_in[9];
    const float* nz1   = (const float*)d_in[10];
    const float* ad1w  = (const float*)d_in[11];
    const float* ad1b  = (const float*)d_in[12];
    const float* W2    = (const float*)d_in[13];
    const float* b2    = (const float*)d_in[14];
    const float* t2w   = (const float*)d_in[15];
    const float* t2b   = (const float*)d_in[16];
    const float* tb2w  = (const float*)d_in[17];
    const float* tb2b  = (const float*)d_in[18];
    const float* nz2   = (const float*)d_in[19];
    const float* ad2w  = (const float*)d_in[20];
    const float* ad2b  = (const float*)d_in[21];
    float* out = (float*)d_out;

    static cudaStream_t s2 = nullptr;
    static cudaEvent_t ev_root = nullptr, ev_pre = nullptr, ev_l2 = nullptr;
    if (s2 == nullptr) {
        cudaStreamCreateWithFlags(&s2, cudaStreamNonBlocking);
        cudaEventCreateWithFlags(&ev_root, cudaEventDisableTiming);
        cudaEventCreateWithFlags(&ev_pre,  cudaEventDisableTiming);
        cudaEventCreateWithFlags(&ev_l2,   cudaEventDisableTiming);
        cudaFuncSetAttribute(conv_mma_kernel,
                             cudaFuncAttributeMaxDynamicSharedMemorySize, SMEM_BYTES);
    }

    cudaEventRecord(ev_root, 0);
    cudaStreamWaitEvent(s2, ev_root, 0);

    modvec_kernel<<<32, 128, 0, s2>>>(task, style, b1, tb1w, tb1b, ad1w, ad1b,
                                      b2, tb2w, tb2b, ad2w, ad2b);
    split_x_kernel<<<(N_SMP*CH*HWPX)/1024, 256, 0, s2>>>(x);
    cudaEventRecord(ev_pre, s2);
    gemm_wmod_kernel<<<512, 128, 0, s2>>>(task, t2w, t2b, 1);
    wfrag_build_kernel<<<dim3(NCHUNK, N_SMP), 256, 0, s2>>>(W2, 1);
    cudaEventRecord(ev_l2, s2);

    gemm_wmod_kernel<<<512, 128>>>(task, t1w, t1b, 0);
    wfrag_build_kernel<<<dim3(NCHUNK, N_SMP), 256>>>(W1, 0);
    cudaStreamWaitEvent(0, ev_pre, 0);
    conv_mma_kernel<<<dim3(64, N_SMP), 128, SMEM_BYTES>>>(0, noise, nz1);
    adain_kernel<<<dim3(4, 4096), 256>>>(0, 1, out);
    cudaStreamWaitEvent(0, ev_l2, 0);
    conv_mma_kernel<<<dim3(64, N_SMP), 128, SMEM_BYTES>>>(1, noise, nz2);
    adain_kernel<<<dim3(4, 4096), 256>>>(1, 0, out);
}

// round 17
// speedup vs baseline: 1.2892x; 1.0055x over previous
#include <cuda_runtime.h>
#include <cuda_bf16.h>
#include <math.h>
#include <stdint.h>

#define N_SMP 32
#define CH    128
#define HWPX  4096
#define KTOT  1152
#define KC    64
#define NCHUNK 18
#define WFRAG_PER_N 73728   // u32 per sample: 18 chunk * 4 kstep * 8 m16 * 32 lane * 4 reg

// ---------------- device scratch (layer-indexed where cross-stream) -------
__device__ uint32_t g_wfh[2][N_SMP * WFRAG_PER_N];
__device__ uint32_t g_wfl[2][N_SMP * WFRAG_PER_N];
__device__ float    g_gam[2][N_SMP * CH * CH];
__device__ float    g_bet[2][N_SMP * CH * CH];
__device__ uint32_t g_xp[N_SMP * CH * HWPX];     // x as (hi|lo<<16) bf16 pair
__device__ float g_y[N_SMP * CH * HWPX];
__device__ float g_stats[2][N_SMP * CH * 2];
__device__ float g_bias[2][N_SMP * CH];
__device__ float g_adg[2][N_SMP * CH];
__device__ float g_adb[2][N_SMP * CH];

// ---------------- small per-sample vectors ----------------
__global__ void modvec_kernel(const float* __restrict__ task, const float* __restrict__ style,
    const float* __restrict__ b1, const float* __restrict__ tb1w, const float* __restrict__ tb1b,
    const float* __restrict__ ad1w, const float* __restrict__ ad1b,
    const float* __restrict__ b2, const float* __restrict__ tb2w, const float* __restrict__ tb2b,
    const float* __restrict__ ad2w, const float* __restrict__ ad2b)
{
    __shared__ float ts[512], ss[512];
    const int n = blockIdx.x;
    const int co = threadIdx.x;
    for (int k = co; k < 512; k += 128) { ts[k] = task[n*512+k]; ss[k] = style[n*512+k]; }
    __syncthreads();
    float a0=0.f,a1=0.f,a2=0.f,a3=0.f,a4=0.f,a5=0.f;
    for (int k = 0; k < 512; k++) {
        float t = ts[k], s = ss[k];
        a0 = fmaf(tb1w[co*512+k],       t, a0);
        a1 = fmaf(ad1w[co*512+k],       s, a1);
        a2 = fmaf(ad1w[(co+128)*512+k], s, a2);
        a3 = fmaf(tb2w[co*512+k],       t, a3);
        a4 = fmaf(ad2w[co*512+k],       s, a4);
        a5 = fmaf(ad2w[(co+128)*512+k], s, a5);
    }
    const float se = 0.0625f;
    g_bias[0][n*128+co] = b1[co] + a0*se + tb1b[co];
    g_adg [0][n*128+co] = a1*se + ad1b[co];
    g_adb [0][n*128+co] = a2*se + ad1b[co+128];
    g_bias[1][n*128+co] = b2[co] + a3*se + tb2b[co];
    g_adg [1][n*128+co] = a4*se + ad2b[co];
    g_adb [1][n*128+co] = a5*se + ad2b[co+128];
}

// ---------------- gamma/beta GEMM, register double-buffered k-loop --------
#define GB_JT 64
#define GB_KC 16
__global__ __launch_bounds__(128)
void gemm_wmod_kernel(const float* __restrict__ task, const float* __restrict__ tw,
                      const float* __restrict__ tb, int layer)
{
    __shared__ float As[GB_KC][GB_JT];
    __shared__ float Bs[GB_KC][32];
    const int tid = threadIdx.x;
    const int jb  = blockIdx.x * GB_JT;
    const int jg  = tid & 15;
    const int ng  = tid >> 4;

    if (blockIdx.x < 64) g_stats[layer][blockIdx.x * 128 + tid] = 0.f;

    // per-thread load geometry (constant across chunks)
    const int la_row0 = (tid*2)     >> 2;        // tw row for t=0
    const int la_kq0  = ((tid*2)     & 3) * 4;
    const int la_row1 = (tid*2 + 1) >> 2;        // tw row for t=1
    const int la_kq1  = ((tid*2 + 1) & 3) * 4;
    const int lb_nn   = tid >> 2;
    const int lb_kq   = (tid & 3) * 4;

    float4 va0, va1, vb;
    // prologue: load chunk 0
    va0 = *(const float4*)(tw + (size_t)(jb + la_row0)*512 + 0 + la_kq0);
    va1 = *(const float4*)(tw + (size_t)(jb + la_row1)*512 + 0 + la_kq1);
    vb  = *(const float4*)(task + (size_t)lb_nn*512 + 0 + lb_kq);

    float acc[4][4] = {};

    for (int k0 = 0; k0 < 512; k0 += GB_KC) {
        // stage current chunk from registers
        As[la_kq0+0][la_row0] = va0.x; As[la_kq0+1][la_row0] = va0.y;
        As[la_kq0+2][la_row0] = va0.z; As[la_kq0+3][la_row0] = va0.w;
        As[la_kq1+0][la_row1] = va1.x; As[la_kq1+1][la_row1] = va1.y;
        As[la_kq1+2][la_row1] = va1.z; As[la_kq1+3][la_row1] = va1.w;
        Bs[lb_kq+0][lb_nn] = vb.x; Bs[lb_kq+1][lb_nn] = vb.y;
        Bs[lb_kq+2][lb_nn] = vb.z; Bs[lb_kq+3][lb_nn] = vb.w;
        __syncthreads();

        // prefetch next chunk (hides DRAM latency under the FMA phase)
        if (k0 + GB_KC < 512) {
            int kn = k0 + GB_KC;
            va0 = *(const float4*)(tw + (size_t)(jb + la_row0)*512 + kn + la_kq0);
            va1 = *(const float4*)(tw + (size_t)(jb + la_row1)*512 + kn + la_kq1);
            vb  = *(const float4*)(task + (size_t)lb_nn*512 + kn + lb_kq);
        }

        #pragma unroll
        for (int k = 0; k < GB_KC; k++) {
            float4 a = *(const float4*)&As[k][jg*4];
            float4 b = *(const float4*)&Bs[k][ng*4];
            float av[4] = {a.x,a.y,a.z,a.w};
            float bv[4] = {b.x,b.y,b.z,b.w};
            #pragma unroll
            for (int i = 0; i < 4; i++)
                #pragma unroll
                for (int j = 0; j < 4; j++)
                    acc[i][j] = fmaf(av[i], bv[j], acc[i][j]);
        }
        __syncthreads();
    }

    const float se = 0.0625f;
    const int co = jb >> 8;
    #pragma unroll
    for (int i = 0; i < 4; i += 2) {
        int jg4  = jb + jg*4 + i;
        int ci   = (jg4 & 255) >> 1;
        float tbg = tb[jg4], tbb_ = tb[jg4+1];
        #pragma unroll
        for (int nn = 0; nn < 4; nn++) {
            int n = ng*4 + nn;
            g_gam[layer][((size_t)n*128 + co)*128 + ci] = acc[i][nn]  * se + tbg;
            g_bet[layer][((size_t)n*128 + co)*128 + ci] = acc[i+1][nn]* se + tbb_;
        }
    }
}

// ---------------- fragment builder: coalesced uint4 stores ----------------
__global__ __launch_bounds__(256)
void wfrag_build_kernel(const float* __restrict__ Wt, int layer)
{
    const int chunk = blockIdx.x;
    const int n     = blockIdx.y;
    const int tid   = threadIdx.x;
    const float swm = 1.0f/24.0f;

    const float* gam = g_gam[layer] + (size_t)n * CH * CH;
    const float* bet = g_bet[layer] + (size_t)n * CH * CH;
    uint32_t* outh = g_wfh[layer] + (size_t)n * WFRAG_PER_N + chunk * 4096;
    uint32_t* outl = g_wfl[layer] + (size_t)n * WFRAG_PER_N + chunk * 4096;

    #pragma unroll
    for (int it = 0; it < 4; it++) {
        int wbase = it*1024 + tid*4;
        uint32_t hq[4], lq[4];
        #pragma unroll
        for (int q = 0; q < 4; q++) {
            int w = wbase + q;
            int reg   = w & 3;
            int ln    = (w >> 2) & 31;
            int m16   = (w >> 7) & 7;
            int kstep = w >> 10;
            int row16 = ((ln >> 2) & 7) | ((reg & 1) << 3);
            int co    = m16*16 + row16;
            int kk16  = ((ln & 3) << 1) | ((reg >> 1) << 3);
            int k0    = chunk*64 + kstep*16 + kk16;
            int k1    = k0 + 1;
            int ci0 = k0/9, k90 = k0 - 9*ci0;
            int ci1 = k1/9, k91 = k1 - 9*ci1;
            float w0 = fmaf(Wt[(co*128 + ci0)*9 + k90], gam[co*128 + ci0], bet[co*128 + ci0]) * swm;
            float w1 = fmaf(Wt[(co*128 + ci1)*9 + k91], gam[co*128 + ci1], bet[co*128 + ci1]) * swm;
            __nv_bfloat16 h0 = __float2bfloat16(w0);
            __nv_bfloat16 h1 = __float2bfloat16(w1);
            __nv_bfloat16 l0 = __float2bfloat16(w0 - __bfloat162float(h0));
            __nv_bfloat16 l1 = __float2bfloat16(w1 - __bfloat162float(h1));
            hq[q] = (uint32_t)__bfloat16_as_ushort(h0) | ((uint32_t)__bfloat16_as_ushort(h1) << 16);
            lq[q] = (uint32_t)__bfloat16_as_ushort(l0) | ((uint32_t)__bfloat16_as_ushort(l1) << 16);
        }
        *(uint4*)(outh + wbase) = make_uint4(hq[0], hq[1], hq[2], hq[3]);
        *(uint4*)(outl + wbase) = make_uint4(lq[0], lq[1], lq[2], lq[3]);
    }
}

// ---------------- x split: f32 -> (bf16 hi | bf16 lo << 16) ----------------
__device__ __forceinline__ uint32_t split_pack(float v) {
    uint32_t b = __float_as_uint(v);
    uint32_t hbits = b & 0xFFFF0000u;
    float l = v - __uint_as_float(hbits);
    uint16_t lb = __bfloat16_as_ushort(__float2bfloat16(l));
    return (b >> 16) | ((uint32_t)lb << 16);
}

__global__ void split_x_kernel(const float* __restrict__ x) {
    int i = blockIdx.x * blockDim.x + threadIdx.x;
    float4 v = ((const float4*)x)[i];
    uint4 o;
    o.x = split_pack(v.x); o.y = split_pack(v.y);
    o.z = split_pack(v.z); o.w = split_pack(v.w);
    ((uint4*)g_xp)[i] = o;
}

// ---------------- mma.sync conv: 128 threads, 128co x 64px, 2 CTAs/SM -----
#define B_WORDS 2048
#define SM_BH 0
#define SM_BL (B_WORDS)
#define SM_NZ (2*B_WORDS)
#define SM_BI (SM_NZ + 64)
#define SM_NW (SM_BI + 128)
#define SM_TAB (SM_NW + 128)
#define SMEM_WORDS (SM_TAB + KTOT)
#define SMEM_BYTES (SMEM_WORDS * 4)

__device__ __forceinline__ void mma16816(float* d, const uint4& a, uint32_t b0, uint32_t b1) {
    asm volatile(
        "mma.sync.aligned.m16n8k16.row.col.f32.bf16.bf16.f32 "
        "{%0,%1,%2,%3}, {%4,%5,%6,%7}, {%8,%9}, {%0,%1,%2,%3};"
        : "+f"(d[0]), "+f"(d[1]), "+f"(d[2]), "+f"(d[3])
        : "r"(a.x), "r"(a.y), "r"(a.z), "r"(a.w), "r"(b0), "r"(b1));
}

__device__ __forceinline__ void prefetch_b(const uint32_t* __restrict__ sm_tab,
                                           const uint32_t* __restrict__ base,
                                           uint32_t vmask, int kc, int bkp0,
                                           uint32_t* bPre)
{
    #pragma unroll
    for (int j = 0; j < 16; j++) {
        int kp = bkp0 + 2*j;
        int k0 = kc + kp*2;
        uint2 t = *(const uint2*)&sm_tab[k0];
        uint32_t p0 = (vmask >> (t.x >> 24)) & 1u;
        uint32_t p1 = (vmask >> (t.y >> 24)) & 1u;
        bPre[2*j]   = p0 ? base[t.x & 0xFFFFFFu] : 0u;
        bPre[2*j+1] = p1 ? base[t.y & 0xFFFFFFu] : 0u;
    }
}

__global__ __launch_bounds__(128, 2)
void conv_mma_kernel(int layer, const float* __restrict__ noise, const float* __restrict__ nzw)
{
    extern __shared__ uint32_t sm[];
    float* s_noise = (float*)(sm + SM_NZ);
    float* s_bias  = (float*)(sm + SM_BI);
    float* s_nw    = (float*)(sm + SM_NW);

    const int tid  = threadIdx.x;
    const int lane = tid & 31;
    const int mrow = tid >> 5;
    const int tile = blockIdx.x;
    const int n    = blockIdx.y;

    const uint32_t* xp  = g_xp + (size_t)n * CH * HWPX;
    const uint32_t* wfh = g_wfh[layer] + (size_t)n * WFRAG_PER_N;
    const uint32_t* wfl = g_wfl[layer] + (size_t)n * WFRAG_PER_N;

    if (tid < 64) s_noise[tid] = noise[(size_t)n*HWPX + tile*64 + tid];
    s_bias[tid] = g_bias[layer][n*128 + tid];
    s_nw[tid]   = nzw[tid] * 0.125f;
    for (int k = tid; k < KTOT; k += 128) {
        int ci = k / 9, r = k - 9*ci, ky = r / 3, kx = r - 3*ky;
        sm[SM_TAB + k] = ((uint32_t)(ky*3 + kx) << 24) | (uint32_t)(ci*HWPX + ky*64 + kx);
    }

    const int bp   = tid & 63;
    const int bkp0 = tid >> 6;
    const int by   = tile;
    const int bx   = bp;
    const uint32_t* gbase = xp + (by - 1)*64 + (bx - 1);
    uint32_t vmask = 0;
    #pragma unroll
    for (int kyx = 0; kyx < 9; kyx++) {
        int ky = kyx / 3, kx = kyx - 3*ky;
        int ya = by + ky - 1, xa = bx + kx - 1;
        if ((unsigned)ya < 64u && (unsigned)xa < 64u) vmask |= (1u << kyx);
    }

    __syncthreads();

    uint32_t bPre[32];
    prefetch_b(sm + SM_TAB, gbase, vmask, 0, bkp0, bPre);

    float acc[2][8][4] = {};
    const int mt0 = mrow*2, mt1 = mrow*2 + 1;

    for (int kci = 0; kci < NCHUNK; kci++) {
        const uint32_t* ah = wfh + kci*4096;
        const uint32_t* al = wfl + kci*4096;
        uint4 Ah[4][2], Al[4][2];
        #pragma unroll
        for (int ks = 0; ks < 4; ks++) {
            Ah[ks][0] = *(const uint4*)&ah[(ks*8 + mt0)*128 + lane*4];
            Ah[ks][1] = *(const uint4*)&ah[(ks*8 + mt1)*128 + lane*4];
            Al[ks][0] = *(const uint4*)&al[(ks*8 + mt0)*128 + lane*4];
            Al[ks][1] = *(const uint4*)&al[(ks*8 + mt1)*128 + lane*4];
        }

        __syncthreads();

        #pragma unroll
        for (int j = 0; j < 16; j++) {
            int kp = bkp0 + 2*j;
            uint32_t u0 = bPre[2*j], u1 = bPre[2*j+1];
            uint32_t hp = __byte_perm(u0, u1, 0x5410);
            uint32_t lp = __byte_perm(u0, u1, 0x7632);
            int kstep = kp >> 3;
            int kk16  = (kp*2) & 15;
            int n8    = bp >> 3;
            int ln    = ((bp & 7) << 2) + ((kk16 & 7) >> 1);
            int reg   = kk16 >> 3;
            int w = (((kstep << 3) + n8)*32 + ln)*2 + reg;
            sm[SM_BH + w] = hp;
            sm[SM_BL + w] = lp;
        }
        __syncthreads();

        if (kci + 1 < NCHUNK)
            prefetch_b(sm + SM_TAB, gbase, vmask, (kci + 1)*KC, bkp0, bPre);

        const uint32_t* BH = sm + SM_BH;
        const uint32_t* BL = sm + SM_BL;
        #pragma unroll
        for (int ks = 0; ks < 4; ks++) {
            #pragma unroll
            for (int j = 0; j < 8; j++) {
                int bidx = (((ks << 3) + j)*32 + lane)*2;
                uint2 bh = *(const uint2*)&BH[bidx];
                uint2 bl = *(const uint2*)&BL[bidx];
                mma16816(acc[0][j], Ah[ks][0], bh.x, bh.y);
                mma16816(acc[1][j], Ah[ks][1], bh.x, bh.y);
                mma16816(acc[0][j], Al[ks][0], bh.x, bh.y);
                mma16816(acc[1][j], Al[ks][1], bh.x, bh.y);
                mma16816(acc[0][j], Ah[ks][0], bl.x, bl.y);
                mma16816(acc[1][j], Ah[ks][1], bl.x, bl.y);
            }
        }
    }

    // ---- epilogue ----
    const int g4 = lane >> 2;
    const int q  = lane & 3;
    float psum[2][2] = {}, psq[2][2] = {};
    #pragma unroll
    for (int m = 0; m < 2; m++) {
        int coA = (mrow*2 + m)*16 + g4;
        int coB = coA + 8;
        float biA = s_bias[coA], nwA = s_nw[coA];
        float biB = s_bias[coB], nwB = s_nw[coB];
        float* rowA = g_y + ((size_t)(n*128 + coA))*HWPX + tile*64;
        float* rowB = g_y + ((size_t)(n*128 + coB))*HWPX + tile*64;
        #pragma unroll
        for (int j = 0; j < 8; j++) {
            int px = j*8 + q*2;
            float nz0 = s_noise[px], nz1 = s_noise[px+1];
            float a0 = acc[m][j][0] + biA + nwA*nz0;
            float a1 = acc[m][j][1] + biA + nwA*nz1;
            float b0 = acc[m][j][2] + biB + nwB*nz0;
            float b1 = acc[m][j][3] + biB + nwB*nz1;
            a0 = (a0 > 0.f) ? a0 : 0.2f*a0;
            a1 = (a1 > 0.f) ? a1 : 0.2f*a1;
            b0 = (b0 > 0.f) ? b0 : 0.2f*b0;
            b1 = (b1 > 0.f) ? b1 : 0.2f*b1;
            *(float2*)(rowA + px) = make_float2(a0, a1);
            *(float2*)(rowB + px) = make_float2(b0, b1);
            psum[m][0] += a0 + a1; psq[m][0] += a0*a0 + a1*a1;
            psum[m][1] += b0 + b1; psq[m][1] += b0*b0 + b1*b1;
        }
    }
    #pragma unroll
    for (int off = 1; off < 4; off <<= 1) {
        #pragma unroll
        for (int m = 0; m < 2; m++)
            #pragma unroll
            for (int h = 0; h < 2; h++) {
                psum[m][h] += __shfl_xor_sync(0xffffffffu, psum[m][h], off);
                psq [m][h] += __shfl_xor_sync(0xffffffffu, psq [m][h], off);
            }
    }
    if (q == 0) {
        #pragma unroll
        for (int m = 0; m < 2; m++)
            #pragma unroll
            for (int h = 0; h < 2; h++) {
                int co = (mrow*2 + m)*16 + g4 + h*8;
                atomicAdd(&g_stats[layer][(n*128+co)*2 + 0], psum[m][h]);
                atomicAdd(&g_stats[layer][(n*128+co)*2 + 1], psq[m][h]);
            }
    }
}

// ---------------- AdaIN (fuses bf16 split for next conv on layer 1) -------
__global__ void adain_kernel(int layer, int to_xp, float* __restrict__ dout)
{
    const int nc = blockIdx.y;
    const int i4 = blockIdx.x * blockDim.x + threadIdx.x;
    float mu  = g_stats[layer][nc*2]   * (1.f/4096.f);
    float var = g_stats[layer][nc*2+1] * (1.f/4096.f) - mu*mu;
    var = fmaxf(var, 0.f);
    float inv = rsqrtf(var + 1e-5f);
    float g = g_adg[layer][nc] * inv;
    float b = g_adb[layer][nc] - g * mu;
    const float4* yin = (const float4*)(g_y + (size_t)nc * HWPX);
    float4 v = yin[i4];
    float4 o;
    o.x = fmaf(g, v.x, b); o.y = fmaf(g, v.y, b);
    o.z = fmaf(g, v.z, b); o.w = fmaf(g, v.w, b);
    if (to_xp) {
        uint4 p;
        p.x = split_pack(o.x); p.y = split_pack(o.y);
        p.z = split_pack(o.z); p.w = split_pack(o.w);
        ((uint4*)(g_xp + (size_t)nc * HWPX))[i4] = p;
    } else {
        ((float4*)(dout + (size_t)nc * HWPX))[i4] = o;
    }
}

// ---------------- launch ----------------
extern "C" void kernel_launch(void* const* d_in, const int* in_sizes, int n_in,
                              void* d_out, int out_size)
{
    const float* x     = (const float*)d_in[0];
    const float* style = (const float*)d_in[1];
    const float* noise = (const float*)d_in[2];
    const float* task  = (const float*)d_in[3];
    const float* W1    = (const float*)d_in[4];
    const float* b1    = (const float*)d_in[5];
    const float* t1w   = (const float*)d_in[6];
    const float* t1b   = (const float*)d_in[7];
    const float* tb1w  = (const float*)d_in[8];
    const float* tb1b  = (const float*)d_in[9];
    const float* nz1   = (const float*)d_in[10];
    const float* ad1w  = (const float*)d_in[11];
    const float* ad1b  = (const float*)d_in[12];
    const float* W2    = (const float*)d_in[13];
    const float* b2    = (const float*)d_in[14];
    const float* t2w   = (const float*)d_in[15];
    const float* t2b   = (const float*)d_in[16];
    const float* tb2w  = (const float*)d_in[17];
    const float* tb2b  = (const float*)d_in[18];
    const float* nz2   = (const float*)d_in[19];
    const float* ad2w  = (const float*)d_in[20];
    const float* ad2b  = (const float*)d_in[21];
    float* out = (float*)d_out;

    static cudaStream_t s2 = nullptr;
    static cudaEvent_t ev_root = nullptr, ev_pre = nullptr, ev_l2 = nullptr, ev_w1 = nullptr;
    if (s2 == nullptr) {
        cudaStreamCreateWithFlags(&s2, cudaStreamNonBlocking);
        cudaEventCreateWithFlags(&ev_root, cudaEventDisableTiming);
        cudaEventCreateWithFlags(&ev_pre,  cudaEventDisableTiming);
        cudaEventCreateWithFlags(&ev_l2,   cudaEventDisableTiming);
        cudaEventCreateWithFlags(&ev_w1,   cudaEventDisableTiming);
        cudaFuncSetAttribute(conv_mma_kernel,
                             cudaFuncAttributeMaxDynamicSharedMemorySize, SMEM_BYTES);
    }

    cudaEventRecord(ev_root, 0);
    cudaStreamWaitEvent(s2, ev_root, 0);

    // s2: prerequisites for conv1 first (no contention with gemm1's DRAM burst)
    modvec_kernel<<<32, 128, 0, s2>>>(task, style, b1, tb1w, tb1b, ad1w, ad1b,
                                      b2, tb2w, tb2b, ad2w, ad2b);
    split_x_kernel<<<(N_SMP*CH*HWPX)/1024, 256, 0, s2>>>(x);
    cudaEventRecord(ev_pre, s2);

    // main: layer-1 producers (run mostly alone) -> conv1 ...
    gemm_wmod_kernel<<<512, 128>>>(task, t1w, t1b, 0);
    wfrag_build_kernel<<<dim3(NCHUNK, N_SMP), 256>>>(W1, 0);
    cudaEventRecord(ev_w1, 0);

    // s2: layer-2 producers deferred until wfrag1 done -> overlap with conv1
    cudaStreamWaitEvent(s2, ev_w1, 0);
    gemm_wmod_kernel<<<512, 128, 0, s2>>>(task, t2w, t2b, 1);
    wfrag_build_kernel<<<dim3(NCHUNK, N_SMP), 256, 0, s2>>>(W2, 1);
    cudaEventRecord(ev_l2, s2);

    cudaStreamWaitEvent(0, ev_pre, 0);
    conv_mma_kernel<<<dim3(64, N_SMP), 128, SMEM_BYTES>>>(0, noise, nz1);
    adain_kernel<<<dim3(4, 4096), 256>>>(0, 1, out);
    cudaStreamWaitEvent(0, ev_l2, 0);
    conv_mma_kernel<<<dim3(64, N_SMP), 128, SMEM_BYTES>>>(1, noise, nz2);
    adain_kernel<<<dim3(4, 4096), 256>>>(1, 0, out);
}